// round 16
// baseline (speedup 1.0000x reference)
#include <cuda_runtime.h>

#define CN 512
#define KK 64
#define NPIX 16384
#define BB 8
#define BN_EPS 1e-5f
#define CNT ((float)(BB * NPIX))

typedef unsigned long long u64;

__device__ __forceinline__ u64 ffma2(u64 a, u64 b, u64 c) {
    u64 d;
    asm("fma.rn.f32x2 %0, %1, %2, %3;" : "=l"(d) : "l"(a), "l"(b), "l"(c));
    return d;
}
__device__ __forceinline__ u64 pack2(float x, float y) {
    u64 v; asm("mov.b64 %0, {%1, %2};" : "=l"(v) : "f"(x), "f"(y)); return v;
}
__device__ __forceinline__ float2 unpack2(u64 v) {
    float2 f; asm("mov.b64 {%0, %1}, %2;" : "=f"(f.x), "=f"(f.y) : "l"(v)); return f;
}
__device__ __forceinline__ void cp16(void* smem_dst, const void* gmem_src) {
    unsigned s = (unsigned)__cvta_generic_to_shared(smem_dst);
    asm volatile("cp.async.cg.shared.global [%0], [%1], 16;" :: "r"(s), "l"(gmem_src));
}
__device__ __forceinline__ float4 ldcs4(const float* p) {
    float4 v;
    asm volatile("ld.global.cs.v4.f32 {%0,%1,%2,%3}, [%4];"
                 : "=f"(v.x), "=f"(v.y), "=f"(v.z), "=f"(v.w) : "l"(p));
    return v;
}
__device__ __forceinline__ void stcs4(float* p, float4 v) {
    asm volatile("st.global.cs.v4.f32 [%0], {%1,%2,%3,%4};"
                 :: "l"(p), "f"(v.x), "f"(v.y), "f"(v.z), "f"(v.w));
}
#define CP_COMMIT asm volatile("cp.async.commit_group;")
#define CP_WAIT0  asm volatile("cp.async.wait_group 0;")
#define CP_WAIT1  asm volatile("cp.async.wait_group 1;")

// ---------------- scratch (static device globals; no allocation) -------------
__device__ float g_W1t[CN * KK];         // (lin0_w @ conv1_w)^T  [c][k]
__device__ float g_b1[KK];               // lin0_w @ conv1_b
__device__ float g_W2t[KK * CN];         // (conv2_w @ lin1_w)^T  [k][c]
__device__ float g_attn[(size_t)BB * KK * NPIX];        // 32 MB (exp, then Atilde)
__device__ float g_rowsum[BB * KK];      // per-row sum of exp
__device__ float g_M[KK * KK];           // sum_b  A~ A~^T
__device__ float g_r[KK];                // sum_{b,n} A~
__device__ float g_scale[CN];
__device__ float g_shift[CN];

// ---------------- 1. tiled prep: folded weights + zero accumulators ---------
__global__ __launch_bounds__(256) void prep_kernel(const float* __restrict__ conv1_w,
                                                   const float* __restrict__ conv1_b,
                                                   const float* __restrict__ lin0_w,
                                                   const float* __restrict__ lin1_w,
                                                   const float* __restrict__ conv2_w) {
    int blk = blockIdx.x;
    int tid = threadIdx.x;
    if (blk < 16) {
        __shared__ float Ct[32][65];
        __shared__ float Lt[32][65];
        int tx = tid & 15, tyc = tid >> 4;
        float acc[4][4];
#pragma unroll
        for (int a = 0; a < 4; a++)
#pragma unroll
            for (int q = 0; q < 4; q++) acc[a][q] = 0.f;
        if (blk < 8) {
            int c0 = blk * 64;
            for (int i0 = 0; i0 < CN; i0 += 32) {
#pragma unroll
                for (int j = 0; j < 8; j++) {
                    int idx = tid + j * 256;
                    { int ii = idx >> 6, cc = idx & 63;
                      Ct[ii][cc] = conv1_w[(i0 + ii) * CN + c0 + cc]; }
                    { int ii = idx & 31, kk = idx >> 5;
                      Lt[ii][kk] = lin0_w[kk * CN + i0 + ii]; }
                }
                __syncthreads();
#pragma unroll
                for (int ii = 0; ii < 32; ii++) {
                    float cv[4], lv[4];
#pragma unroll
                    for (int a = 0; a < 4; a++) cv[a] = Ct[ii][tyc * 4 + a];
#pragma unroll
                    for (int q = 0; q < 4; q++) lv[q] = Lt[ii][tx * 4 + q];
#pragma unroll
                    for (int a = 0; a < 4; a++)
#pragma unroll
                        for (int q = 0; q < 4; q++) acc[a][q] = fmaf(cv[a], lv[q], acc[a][q]);
                }
                __syncthreads();
            }
#pragma unroll
            for (int a = 0; a < 4; a++)
#pragma unroll
                for (int q = 0; q < 4; q++)
                    g_W1t[(c0 + tyc * 4 + a) * KK + tx * 4 + q] = acc[a][q];
        } else {
            int c0 = (blk - 8) * 64;
            for (int i0 = 0; i0 < CN; i0 += 32) {
#pragma unroll
                for (int j = 0; j < 8; j++) {
                    int idx = tid + j * 256;
                    { int ii = idx & 31, cc = idx >> 5;
                      Ct[ii][cc] = conv2_w[(c0 + cc) * CN + i0 + ii]; }
                    { int kk = idx & 63, ii = idx >> 6;
                      Lt[ii][kk] = lin1_w[(i0 + ii) * KK + kk]; }
                }
                __syncthreads();
#pragma unroll
                for (int ii = 0; ii < 32; ii++) {
                    float lv[4], cv[4];
#pragma unroll
                    for (int a = 0; a < 4; a++) lv[a] = Lt[ii][tx * 4 + a];
#pragma unroll
                    for (int q = 0; q < 4; q++) cv[q] = Ct[ii][tyc * 4 + q];
#pragma unroll
                    for (int a = 0; a < 4; a++)
#pragma unroll
                        for (int q = 0; q < 4; q++) acc[a][q] = fmaf(lv[a], cv[q], acc[a][q]);
                }
                __syncthreads();
            }
#pragma unroll
            for (int a = 0; a < 4; a++)
#pragma unroll
                for (int q = 0; q < 4; q++)
                    g_W2t[(tx * 4 + a) * CN + c0 + tyc * 4 + q] = acc[a][q];
        }
    } else {
        if (tid < KK) {
            float s = 0.f;
            for (int i = 0; i < CN; i++) s = fmaf(lin0_w[tid * CN + i], conv1_b[i], s);
            g_b1[tid] = s;
        }
        for (int i = tid; i < KK * KK; i += 256) g_M[i] = 0.f;
        if (tid < KK) g_r[tid] = 0.f;
        for (int i = tid; i < BB * KK; i += 256) g_rowsum[i] = 0.f;
    }
}

// ---------------- 2. attn exp = exp(W1 @ x + b1); rowsum atomics ------------
// wdup built in-kernel (single 16KB buffer, reg-prefetched weights) -> no packs
#define A_TN 256
#define A_CH 32
#define A_NC (CN / A_CH)
#define A_SMEM (2 * A_CH * A_TN * 4 + A_CH * KK * 8)   // 64KB + 16KB = 80KB
__global__ __launch_bounds__(256) void attn_gemm_kernel(const float* __restrict__ x) {
    extern __shared__ __align__(16) char sm_a[];
    float (*xs)[A_CH][A_TN] = (float (*)[A_CH][A_TN])sm_a;
    u64 (*wdup)[KK]         = (u64 (*)[KK])(sm_a + 2 * A_CH * A_TN * 4);  // [32][64]

    int b = blockIdx.y;
    int n0 = blockIdx.x * A_TN;
    int tid = threadIdx.x;
    int tx = tid & 31;   // n-group — whole warp shares one ty (broadcast w)
    int ty = tid >> 5;   // k-group
    const float* xb = x + (size_t)b * CN * NPIX;

    u64 acc[8][4];
#pragma unroll
    for (int i = 0; i < 8; i++)
#pragma unroll
        for (int j = 0; j < 4; j++) acc[i][j] = 0ull;

    auto stage_x = [&](int ch, int bf) {
        int c0 = ch * A_CH;
#pragma unroll
        for (int j = 0; j < 8; j++) {           // 32x256 floats = 2048 float4 ✓
            int i4 = tid + j * 256;
            int cc = i4 >> 6, nn4 = i4 & 63;
            cp16(&xs[bf][cc][nn4 * 4], &xb[(size_t)(c0 + cc) * NPIX + n0 + nn4 * 4]);
        }
    };
    float wreg[8];
    auto load_w = [&](int ch) {                 // 8 coalesced LDG.32 (k-contig)
        int c0 = ch * A_CH;
#pragma unroll
        for (int j = 0; j < 8; j++) {
            int idx = tid + j * 256;            // 2048 = 32x64 ✓
            int cc = idx >> 6, k = idx & 63;
            wreg[j] = g_W1t[(c0 + cc) * KK + k];
        }
    };
    auto store_wdup = [&]() {
#pragma unroll
        for (int j = 0; j < 8; j++) {
            int idx = tid + j * 256;
            int cc = idx >> 6, k = idx & 63;
            wdup[cc][k] = pack2(wreg[j], wreg[j]);
        }
    };

    stage_x(0, 0);
    CP_COMMIT;
    load_w(0);
    for (int ch = 0; ch < A_NC; ch++) {
        int cur = ch & 1;
        store_wdup();                            // prev compute done (trailing sync)
        if (ch + 1 < A_NC) {
            stage_x(ch + 1, cur ^ 1);
            CP_COMMIT;
            load_w(ch + 1);                      // LDG latency hidden by compute
            CP_WAIT1;
        } else {
            CP_WAIT0;
        }
        __syncthreads();                         // xs[cur] + wdup ready
#pragma unroll 8
        for (int cc = 0; cc < A_CH; cc++) {
            ulonglong2 xa = *(const ulonglong2*)&xs[cur][cc][tx * 8];
            ulonglong2 xc = *(const ulonglong2*)&xs[cur][cc][tx * 8 + 4];
            u64 xv[4] = {xa.x, xa.y, xc.x, xc.y};
            ulonglong2 wa = *(const ulonglong2*)&wdup[cc][ty * 8];       // broadcast
            ulonglong2 wb = *(const ulonglong2*)&wdup[cc][ty * 8 + 2];
            ulonglong2 wc = *(const ulonglong2*)&wdup[cc][ty * 8 + 4];
            ulonglong2 wd = *(const ulonglong2*)&wdup[cc][ty * 8 + 6];
            u64 wv[8] = {wa.x, wa.y, wb.x, wb.y, wc.x, wc.y, wd.x, wd.y};
#pragma unroll
            for (int ki = 0; ki < 8; ki++)
#pragma unroll
                for (int jp = 0; jp < 4; jp++)
                    acc[ki][jp] = ffma2(wv[ki], xv[jp], acc[ki][jp]);
        }
        __syncthreads();                         // before next store_wdup overwrite
    }
    // epilogue: exp(v + b1) (no-max softmax numerator), store, rowsum atomics
#pragma unroll
    for (int ki = 0; ki < 8; ki++) {
        int k = ty * 8 + ki;
        float bb = g_b1[k];
        float2 r0 = unpack2(acc[ki][0]), r1 = unpack2(acc[ki][1]);
        float2 r2 = unpack2(acc[ki][2]), r3 = unpack2(acc[ki][3]);
        float4 o0 = {__expf(r0.x + bb), __expf(r0.y + bb),
                     __expf(r1.x + bb), __expf(r1.y + bb)};
        float4 o1 = {__expf(r2.x + bb), __expf(r2.y + bb),
                     __expf(r3.x + bb), __expf(r3.y + bb)};
        float* p = g_attn + (size_t)(b * KK + k) * NPIX + n0 + tx * 8;
        *(float4*)p = o0;
        *(float4*)(p + 4) = o1;
        float s = o0.x + o0.y + o0.z + o0.w + o1.x + o1.y + o1.z + o1.w;
#pragma unroll
        for (int o = 16; o > 0; o >>= 1) s += __shfl_xor_sync(0xffffffffu, s, o);
        if (tx == 0) atomicAdd(&g_rowsum[b * KK + k], s);
    }
}

// ---------------- 3. stats + full renorm: writes Atilde, accumulates M,r ----
#define S_TN 256
#define S_STRIDE (S_TN + 1)
#define S_SMEM (KK * S_STRIDE * 4)        // ~65.8 KB
__global__ __launch_bounds__(256) void stats_kernel() {
    extern __shared__ __align__(16) float as[];    // [KK][S_STRIDE]
    __shared__ float invrow[KK];
    int b = blockIdx.y;
    int n0 = blockIdx.x * S_TN;
    int tid = threadIdx.x;
    float* ab = g_attn + (size_t)b * KK * NPIX + n0;

    if (tid < KK) invrow[tid] = 1.f / g_rowsum[b * KK + tid];
#pragma unroll
    for (int j = 0; j < 16; j++) {            // 4096 float4 = 64x256 ✓
        int i4 = tid + j * 256;
        int kk = i4 >> 6, nn4 = i4 & 63;
        float4 v = *(const float4*)&ab[(size_t)kk * NPIX + nn4 * 4];
        float* d = &as[kk * S_STRIDE + nn4 * 4];
        d[0] = v.x; d[1] = v.y; d[2] = v.z; d[3] = v.w;
    }
    __syncthreads();

    {
        float s = 0.f;
#pragma unroll
        for (int k = 0; k < KK; k++) {
            float v = as[k * S_STRIDE + tid] * invrow[k];
            as[k * S_STRIDE + tid] = v;
            s += v;
        }
        float inv = 1.f / (1e-9f + s);
#pragma unroll
        for (int k = 0; k < KK; k++) as[k * S_STRIDE + tid] *= inv;
    }
    __syncthreads();

#pragma unroll
    for (int j = 0; j < 16; j++) {            // write back Atilde ✓
        int i4 = tid + j * 256;
        int kk = i4 >> 6, nn4 = i4 & 63;
        float* s = &as[kk * S_STRIDE + nn4 * 4];
        float4 v = {s[0], s[1], s[2], s[3]};
        *(float4*)&ab[(size_t)kk * NPIX + nn4 * 4] = v;
    }

    if (tid < KK) {
        float rs = 0.f;
        int base = tid * S_STRIDE;
        int start = (tid * 5) & (S_TN - 1);
#pragma unroll 8
        for (int t = 0; t < S_TN; t++) {
            int nn = start + t; if (nn >= S_TN) nn -= S_TN;
            rs += as[base + nn];
        }
        atomicAdd(&g_r[tid], rs);
    }

    int jt = tid & 15, it = tid >> 4;
    float Ml[4][4];
#pragma unroll
    for (int a = 0; a < 4; a++)
#pragma unroll
        for (int q = 0; q < 4; q++) Ml[a][q] = 0.f;
#pragma unroll 4
    for (int nn = 0; nn < S_TN; nn++) {
        float ai[4], aj[4];
#pragma unroll
        for (int a = 0; a < 4; a++) ai[a] = as[(it * 4 + a) * S_STRIDE + nn];
#pragma unroll
        for (int q = 0; q < 4; q++) aj[q] = as[(jt * 4 + q) * S_STRIDE + nn];
#pragma unroll
        for (int a = 0; a < 4; a++)
#pragma unroll
            for (int q = 0; q < 4; q++) Ml[a][q] = fmaf(ai[a], aj[q], Ml[a][q]);
    }
#pragma unroll
    for (int a = 0; a < 4; a++)
#pragma unroll
        for (int q = 0; q < 4; q++)
            atomicAdd(&g_M[(it * 4 + a) * KK + jt * 4 + q], Ml[a][q]);
}

// ---------------- 4. BN scale/shift from quadratic form ---------------------
__global__ __launch_bounds__(128) void bnscale_kernel(const float* __restrict__ gamma,
                                                      const float* __restrict__ beta) {
    __shared__ float Msh[KK * KK];
    int tid = threadIdx.x;
#pragma unroll
    for (int j = 0; j < KK * KK / 128; j++) Msh[tid + j * 128] = g_M[tid + j * 128];
    __syncthreads();

    int c = blockIdx.x * 128 + tid;
    float w[KK];
#pragma unroll
    for (int k = 0; k < KK; k++) w[k] = g_W2t[k * CN + c];
    float mean = 0.f;
#pragma unroll
    for (int k = 0; k < KK; k++) mean = fmaf(w[k], g_r[k], mean);
    mean /= CNT;
    float sumsq = 0.f;
#pragma unroll 2
    for (int i = 0; i < KK; i++) {
        float t = 0.f;
#pragma unroll
        for (int j = 0; j < KK; j++) t = fmaf(Msh[i * KK + j], w[j], t);
        sumsq = fmaf(w[i], t, sumsq);
    }
    float var = sumsq / CNT - mean * mean;
    float sc = gamma[c] * rsqrtf(var + BN_EPS);
    g_scale[c] = sc;
    g_shift[c] = beta[c] - mean * sc;
}

// ---------------- 5. fused: out = relu((W2 @ Atilde)*sc + sh + x) -----------
#define B_TN 128
#define B_TC 128
#define B_SMEM (KK * B_TN * 4 + 2 * KK * B_TC * 4)   // 96KB
__global__ __launch_bounds__(256) void out_fused_kernel(const float* __restrict__ x,
                                                        float* __restrict__ out) {
    extern __shared__ __align__(16) char sm_b[];
    float (*as)[B_TN]     = (float (*)[B_TN])sm_b;                          // 32KB
    float (*ws)[KK][B_TC] = (float (*)[KK][B_TC])(sm_b + KK * B_TN * 4);    // 2x32KB

    int b = blockIdx.y;
    int n0 = blockIdx.x * B_TN;
    int tid = threadIdx.x;
    int tx = tid & 15, ty = tid >> 4;
    const float* ab = g_attn + (size_t)b * KK * NPIX;

#pragma unroll
    for (int j = 0; j < 8; j++) {
        int i4 = tid + j * 256;
        int kk = i4 >> 5, nn4 = i4 & 31;
        cp16(&as[kk][nn4 * 4], &ab[(size_t)kk * NPIX + n0 + nn4 * 4]);
    }
#pragma unroll
    for (int j = 0; j < 8; j++) {
        int i4 = tid + j * 256;
        int kk = i4 >> 5, cc4 = i4 & 31;
        cp16(&ws[0][kk][cc4 * 4], &g_W2t[kk * CN + cc4 * 4]);
    }
    CP_COMMIT;
    CP_WAIT0;
    __syncthreads();

    for (int cb = 0; cb < CN / B_TC; cb++) {
        int cur = cb & 1;
        if (cb + 1 < CN / B_TC) {
#pragma unroll
            for (int j = 0; j < 8; j++) {
                int i4 = tid + j * 256;
                int kk = i4 >> 5, cc4 = i4 & 31;
                cp16(&ws[cur ^ 1][kk][cc4 * 4],
                     &g_W2t[kk * CN + (cb + 1) * B_TC + cc4 * 4]);
            }
            CP_COMMIT;
        }
        u64 acc[8][4];
#pragma unroll
        for (int i = 0; i < 8; i++)
#pragma unroll
            for (int j = 0; j < 4; j++) acc[i][j] = 0ull;
#pragma unroll 8
        for (int kk = 0; kk < KK; kk++) {
            ulonglong2 aa = *(const ulonglong2*)&as[kk][tx * 8];
            ulonglong2 ac = *(const ulonglong2*)&as[kk][tx * 8 + 4];
            u64 av[4] = {aa.x, aa.y, ac.x, ac.y};
            float4 w0 = *(const float4*)&ws[cur][kk][ty * 8];
            float4 w1 = *(const float4*)&ws[cur][kk][ty * 8 + 4];
            u64 wv[8] = {pack2(w0.x, w0.x), pack2(w0.y, w0.y),
                         pack2(w0.z, w0.z), pack2(w0.w, w0.w),
                         pack2(w1.x, w1.x), pack2(w1.y, w1.y),
                         pack2(w1.z, w1.z), pack2(w1.w, w1.w)};
#pragma unroll
            for (int ki = 0; ki < 8; ki++)
#pragma unroll
                for (int jp = 0; jp < 4; jp++)
                    acc[ki][jp] = ffma2(wv[ki], av[jp], acc[ki][jp]);
        }
        int c0 = cb * B_TC;
#pragma unroll
        for (int ki = 0; ki < 8; ki++) {
            int c = c0 + ty * 8 + ki;
            float sc = g_scale[c], sh = g_shift[c];
            float2 y0 = unpack2(acc[ki][0]), y1 = unpack2(acc[ki][1]);
            float2 y2 = unpack2(acc[ki][2]), y3 = unpack2(acc[ki][3]);
            size_t off = ((size_t)(b * CN + c)) * NPIX + n0 + tx * 8;
            float4 x0 = ldcs4(&x[off]);
            float4 x1 = ldcs4(&x[off + 4]);
            float4 o0, o1;
            o0.x = fmaxf(fmaf(y0.x, sc, sh) + x0.x, 0.f);
            o0.y = fmaxf(fmaf(y0.y, sc, sh) + x0.y, 0.f);
            o0.z = fmaxf(fmaf(y1.x, sc, sh) + x0.z, 0.f);
            o0.w = fmaxf(fmaf(y1.y, sc, sh) + x0.w, 0.f);
            o1.x = fmaxf(fmaf(y2.x, sc, sh) + x1.x, 0.f);
            o1.y = fmaxf(fmaf(y2.y, sc, sh) + x1.y, 0.f);
            o1.z = fmaxf(fmaf(y3.x, sc, sh) + x1.z, 0.f);
            o1.w = fmaxf(fmaf(y3.y, sc, sh) + x1.w, 0.f);
            stcs4(&out[off], o0);
            stcs4(&out[off + 4], o1);
        }
        if (cb + 1 < CN / B_TC) { CP_WAIT0; __syncthreads(); }
    }
}

// ---------------- launch -----------------------------------------------------
extern "C" void kernel_launch(void* const* d_in, const int* in_sizes, int n_in,
                              void* d_out, int out_size) {
    const float* x       = (const float*)d_in[0];
    const float* conv1_w = (const float*)d_in[1];
    const float* conv1_b = (const float*)d_in[2];
    const float* lin0_w  = (const float*)d_in[3];
    const float* lin1_w  = (const float*)d_in[4];
    const float* conv2_w = (const float*)d_in[5];
    const float* gamma   = (const float*)d_in[6];
    const float* beta    = (const float*)d_in[7];
    float* out = (float*)d_out;

    cudaFuncSetAttribute(attn_gemm_kernel,
                         cudaFuncAttributeMaxDynamicSharedMemorySize, A_SMEM);
    cudaFuncSetAttribute(stats_kernel,
                         cudaFuncAttributeMaxDynamicSharedMemorySize, S_SMEM);
    cudaFuncSetAttribute(out_fused_kernel,
                         cudaFuncAttributeMaxDynamicSharedMemorySize, B_SMEM);

    prep_kernel<<<17, 256>>>(conv1_w, conv1_b, lin0_w, lin1_w, conv2_w);
    attn_gemm_kernel<<<dim3(NPIX / A_TN, BB), 256, A_SMEM>>>(x);
    stats_kernel<<<dim3(NPIX / S_TN, BB), 256, S_SMEM>>>();
    bnscale_kernel<<<CN / 128, 128>>>(gamma, beta);
    out_fused_kernel<<<dim3(NPIX / B_TN, BB), 256, B_SMEM>>>(x, out);
}

// round 17
// speedup vs baseline: 1.0870x; 1.0870x over previous
#include <cuda_runtime.h>

#define CN 512
#define KK 64
#define NPIX 16384
#define BB 8
#define BN_EPS 1e-5f
#define CNT ((float)(BB * NPIX))

typedef unsigned long long u64;

__device__ __forceinline__ u64 ffma2(u64 a, u64 b, u64 c) {
    u64 d;
    asm("fma.rn.f32x2 %0, %1, %2, %3;" : "=l"(d) : "l"(a), "l"(b), "l"(c));
    return d;
}
__device__ __forceinline__ u64 pack2(float x, float y) {
    u64 v; asm("mov.b64 %0, {%1, %2};" : "=l"(v) : "f"(x), "f"(y)); return v;
}
__device__ __forceinline__ float2 unpack2(u64 v) {
    float2 f; asm("mov.b64 {%0, %1}, %2;" : "=f"(f.x), "=f"(f.y) : "l"(v)); return f;
}
__device__ __forceinline__ void cp16(void* smem_dst, const void* gmem_src) {
    unsigned s = (unsigned)__cvta_generic_to_shared(smem_dst);
    asm volatile("cp.async.cg.shared.global [%0], [%1], 16;" :: "r"(s), "l"(gmem_src));
}
#define CP_COMMIT asm volatile("cp.async.commit_group;")
#define CP_WAIT0  asm volatile("cp.async.wait_group 0;")
#define CP_WAIT1  asm volatile("cp.async.wait_group 1;")

// ---------------- scratch (static device globals; no allocation) -------------
__device__ float g_W1t[CN * KK];         // (lin0_w @ conv1_w)^T  [c][k]
__device__ float g_b1[KK];               // lin0_w @ conv1_b
__device__ float g_W2t[KK * CN];         // (conv2_w @ lin1_w)^T  [k][c]
__device__ float g_attn[(size_t)BB * KK * NPIX];        // 32 MB (exp, then Atilde)
__device__ float g_rowsum[BB * KK];      // per-row sum of exp
__device__ float g_M[KK * KK];           // sum_b  A~ A~^T
__device__ float g_r[KK];                // sum_{b,n} A~
__device__ float g_scale[CN];
__device__ float g_shift[CN];

// ---------------- 1. tiled prep: folded weights + zero accumulators ---------
// blocks 0-7: W1t c-tiles; 8-15: W2t c-tiles; 16: b1 + zeroing
__global__ __launch_bounds__(256) void prep_kernel(const float* __restrict__ conv1_w,
                                                   const float* __restrict__ conv1_b,
                                                   const float* __restrict__ lin0_w,
                                                   const float* __restrict__ lin1_w,
                                                   const float* __restrict__ conv2_w) {
    int blk = blockIdx.x;
    int tid = threadIdx.x;
    if (blk < 16) {
        __shared__ float Ct[32][65];
        __shared__ float Lt[32][65];
        int tx = tid & 15, tyc = tid >> 4;
        float acc[4][4];
#pragma unroll
        for (int a = 0; a < 4; a++)
#pragma unroll
            for (int q = 0; q < 4; q++) acc[a][q] = 0.f;
        if (blk < 8) {
            // W1t[c][k] = sum_i lin0_w[k*CN+i] * conv1_w[i*CN+c], c tile = blk*64
            int c0 = blk * 64;
            for (int i0 = 0; i0 < CN; i0 += 32) {
#pragma unroll
                for (int j = 0; j < 8; j++) {            // 2048 elems each matrix
                    int idx = tid + j * 256;
                    { int ii = idx >> 6, cc = idx & 63;   // Ct coalesced in cc
                      Ct[ii][cc] = conv1_w[(i0 + ii) * CN + c0 + cc]; }
                    { int ii = idx & 31, kk = idx >> 5;   // Lt coalesced in ii
                      Lt[ii][kk] = lin0_w[kk * CN + i0 + ii]; }
                }
                __syncthreads();
#pragma unroll
                for (int ii = 0; ii < 32; ii++) {
                    float cv[4], lv[4];
#pragma unroll
                    for (int a = 0; a < 4; a++) cv[a] = Ct[ii][tyc * 4 + a];
#pragma unroll
                    for (int q = 0; q < 4; q++) lv[q] = Lt[ii][tx * 4 + q];
#pragma unroll
                    for (int a = 0; a < 4; a++)
#pragma unroll
                        for (int q = 0; q < 4; q++) acc[a][q] = fmaf(cv[a], lv[q], acc[a][q]);
                }
                __syncthreads();
            }
#pragma unroll
            for (int a = 0; a < 4; a++)
#pragma unroll
                for (int q = 0; q < 4; q++)
                    g_W1t[(c0 + tyc * 4 + a) * KK + tx * 4 + q] = acc[a][q];
        } else {
            // W2t[k][c] = sum_i conv2_w[c*CN+i] * lin1_w[i*KK+k], c tile = (blk-8)*64
            int c0 = (blk - 8) * 64;
            for (int i0 = 0; i0 < CN; i0 += 32) {
#pragma unroll
                for (int j = 0; j < 8; j++) {
                    int idx = tid + j * 256;
                    { int ii = idx & 31, cc = idx >> 5;   // conv2_w rows coalesced in ii
                      Ct[ii][cc] = conv2_w[(c0 + cc) * CN + i0 + ii]; }
                    { int kk = idx & 63, ii = idx >> 6;   // lin1_w coalesced in kk
                      Lt[ii][kk] = lin1_w[(i0 + ii) * KK + kk]; }
                }
                __syncthreads();
#pragma unroll
                for (int ii = 0; ii < 32; ii++) {
                    float lv[4], cv[4];
#pragma unroll
                    for (int a = 0; a < 4; a++) lv[a] = Lt[ii][tx * 4 + a];    // k
#pragma unroll
                    for (int q = 0; q < 4; q++) cv[q] = Ct[ii][tyc * 4 + q];   // c
#pragma unroll
                    for (int a = 0; a < 4; a++)
#pragma unroll
                        for (int q = 0; q < 4; q++) acc[a][q] = fmaf(lv[a], cv[q], acc[a][q]);
                }
                __syncthreads();
            }
#pragma unroll
            for (int a = 0; a < 4; a++)
#pragma unroll
                for (int q = 0; q < 4; q++)
                    g_W2t[(tx * 4 + a) * CN + c0 + tyc * 4 + q] = acc[a][q];
        }
    } else {
        // b1 + zero M, r, rowsum
        if (tid < KK) {
            float s = 0.f;
            for (int i = 0; i < CN; i++) s = fmaf(lin0_w[tid * CN + i], conv1_b[i], s);
            g_b1[tid] = s;
        }
        for (int i = tid; i < KK * KK; i += 256) g_M[i] = 0.f;
        if (tid < KK) g_r[tid] = 0.f;
        for (int i = tid; i < BB * KK; i += 256) g_rowsum[i] = 0.f;
    }
}

// ---------------- 2. attn exp = exp(W1 @ x + b1); rowsum atomics ------------
#define A_TN 256
#define A_CH 32
#define A_NC (CN / A_CH)
#define A_SMEM (2 * A_CH * A_TN * 4 + 2 * A_CH * KK * 4)   // 80KB
__global__ __launch_bounds__(256) void attn_gemm_kernel(const float* __restrict__ x) {
    extern __shared__ __align__(16) char sm_a[];
    float (*xs)[A_CH][A_TN] = (float (*)[A_CH][A_TN])sm_a;
    float (*ws)[A_CH][KK]   = (float (*)[A_CH][KK])(sm_a + 2 * A_CH * A_TN * 4);

    int b = blockIdx.y;
    int n0 = blockIdx.x * A_TN;
    int tid = threadIdx.x;
    int tx = tid & 31;
    int ty = tid >> 5;
    const float* xb = x + (size_t)b * CN * NPIX;

    u64 acc[8][4];
#pragma unroll
    for (int i = 0; i < 8; i++)
#pragma unroll
        for (int j = 0; j < 4; j++) acc[i][j] = 0ull;

    auto stage = [&](int ch, int bf) {
        int c0 = ch * A_CH;
#pragma unroll
        for (int j = 0; j < 8; j++) {           // 2048 float4 ✓
            int i4 = tid + j * 256;
            int cc = i4 >> 6, nn4 = i4 & 63;
            cp16(&xs[bf][cc][nn4 * 4], &xb[(size_t)(c0 + cc) * NPIX + n0 + nn4 * 4]);
        }
#pragma unroll
        for (int j = 0; j < 2; j++) {           // 512 float4 ✓
            int i4 = tid + j * 256;
            int cc = i4 >> 4, k4 = i4 & 15;
            cp16(&ws[bf][cc][k4 * 4], &g_W1t[(c0 + cc) * KK + k4 * 4]);
        }
    };

    stage(0, 0);
    CP_COMMIT;
    for (int ch = 0; ch < A_NC; ch++) {
        int cur = ch & 1;
        if (ch + 1 < A_NC) { stage(ch + 1, cur ^ 1); CP_COMMIT; CP_WAIT1; }
        else               { CP_WAIT0; }
        __syncthreads();
#pragma unroll 8
        for (int cc = 0; cc < A_CH; cc++) {
            ulonglong2 xa = *(const ulonglong2*)&xs[cur][cc][tx * 8];
            ulonglong2 xc = *(const ulonglong2*)&xs[cur][cc][tx * 8 + 4];
            u64 xv[4] = {xa.x, xa.y, xc.x, xc.y};
            float4 w0 = *(const float4*)&ws[cur][cc][ty * 8];
            float4 w1 = *(const float4*)&ws[cur][cc][ty * 8 + 4];
            u64 wv[8] = {pack2(w0.x, w0.x), pack2(w0.y, w0.y),
                         pack2(w0.z, w0.z), pack2(w0.w, w0.w),
                         pack2(w1.x, w1.x), pack2(w1.y, w1.y),
                         pack2(w1.z, w1.z), pack2(w1.w, w1.w)};
#pragma unroll
            for (int ki = 0; ki < 8; ki++)
#pragma unroll
                for (int jp = 0; jp < 4; jp++)
                    acc[ki][jp] = ffma2(wv[ki], xv[jp], acc[ki][jp]);
        }
        __syncthreads();
    }
    // epilogue: exp(v + b1) (no-max softmax numerator), store, rowsum atomics
#pragma unroll
    for (int ki = 0; ki < 8; ki++) {
        int k = ty * 8 + ki;
        float bb = g_b1[k];
        float2 r0 = unpack2(acc[ki][0]), r1 = unpack2(acc[ki][1]);
        float2 r2 = unpack2(acc[ki][2]), r3 = unpack2(acc[ki][3]);
        float4 o0 = {__expf(r0.x + bb), __expf(r0.y + bb),
                     __expf(r1.x + bb), __expf(r1.y + bb)};
        float4 o1 = {__expf(r2.x + bb), __expf(r2.y + bb),
                     __expf(r3.x + bb), __expf(r3.y + bb)};
        float* p = g_attn + (size_t)(b * KK + k) * NPIX + n0 + tx * 8;
        *(float4*)p = o0;
        *(float4*)(p + 4) = o1;
        float s = o0.x + o0.y + o0.z + o0.w + o1.x + o1.y + o1.z + o1.w;
#pragma unroll
        for (int o = 16; o > 0; o >>= 1) s += __shfl_xor_sync(0xffffffffu, s, o);
        if (tx == 0) atomicAdd(&g_rowsum[b * KK + k], s);
    }
}

// ---------------- 3. stats + full renorm: writes Atilde, accumulates M,r ----
#define S_TN 256
#define S_STRIDE (S_TN + 1)
#define S_SMEM (KK * S_STRIDE * 4)        // ~65.8 KB
__global__ __launch_bounds__(256) void stats_kernel() {
    extern __shared__ __align__(16) float as[];    // [KK][S_STRIDE]
    __shared__ float invrow[KK];
    int b = blockIdx.y;
    int n0 = blockIdx.x * S_TN;
    int tid = threadIdx.x;
    float* ab = g_attn + (size_t)b * KK * NPIX + n0;

    if (tid < KK) invrow[tid] = 1.f / g_rowsum[b * KK + tid];
    // stage 64 x 256 floats = 4096 float4 (16 x 256 ✓)
#pragma unroll
    for (int j = 0; j < 16; j++) {
        int i4 = tid + j * 256;
        int kk = i4 >> 6, nn4 = i4 & 63;
        float4 v = *(const float4*)&ab[(size_t)kk * NPIX + nn4 * 4];
        float* d = &as[kk * S_STRIDE + nn4 * 4];
        d[0] = v.x; d[1] = v.y; d[2] = v.z; d[3] = v.w;
    }
    __syncthreads();

    // per-column: softmax-normalize rows, then L1-renorm over k (thread = col)
    {
        float s = 0.f;
#pragma unroll
        for (int k = 0; k < KK; k++) {
            float v = as[k * S_STRIDE + tid] * invrow[k];
            as[k * S_STRIDE + tid] = v;
            s += v;
        }
        float inv = 1.f / (1e-9f + s);
#pragma unroll
        for (int k = 0; k < KK; k++) as[k * S_STRIDE + tid] *= inv;
    }
    __syncthreads();

    // write back Atilde (same pattern as staging ✓)
#pragma unroll
    for (int j = 0; j < 16; j++) {
        int i4 = tid + j * 256;
        int kk = i4 >> 6, nn4 = i4 & 63;
        float* s = &as[kk * S_STRIDE + nn4 * 4];
        float4 v = {s[0], s[1], s[2], s[3]};
        *(float4*)&ab[(size_t)kk * NPIX + nn4 * 4] = v;
    }

    // row sums -> g_r  (threads 0..63, staggered)
    if (tid < KK) {
        float rs = 0.f;
        int base = tid * S_STRIDE;
        int start = (tid * 5) & (S_TN - 1);
#pragma unroll 8
        for (int t = 0; t < S_TN; t++) {
            int nn = start + t; if (nn >= S_TN) nn -= S_TN;
            rs += as[base + nn];
        }
        atomicAdd(&g_r[tid], rs);
    }

    // outer product: thread (it,jt) owns 4x4 of M
    int jt = tid & 15, it = tid >> 4;
    float Ml[4][4];
#pragma unroll
    for (int a = 0; a < 4; a++)
#pragma unroll
        for (int q = 0; q < 4; q++) Ml[a][q] = 0.f;
#pragma unroll 4
    for (int nn = 0; nn < S_TN; nn++) {
        float ai[4], aj[4];
#pragma unroll
        for (int a = 0; a < 4; a++) ai[a] = as[(it * 4 + a) * S_STRIDE + nn];
#pragma unroll
        for (int q = 0; q < 4; q++) aj[q] = as[(jt * 4 + q) * S_STRIDE + nn];
#pragma unroll
        for (int a = 0; a < 4; a++)
#pragma unroll
            for (int q = 0; q < 4; q++) Ml[a][q] = fmaf(ai[a], aj[q], Ml[a][q]);
    }
#pragma unroll
    for (int a = 0; a < 4; a++)
#pragma unroll
        for (int q = 0; q < 4; q++)
            atomicAdd(&g_M[(it * 4 + a) * KK + jt * 4 + q], Ml[a][q]);
}

// ---------------- 4. BN scale/shift from quadratic form ---------------------
__global__ __launch_bounds__(128) void bnscale_kernel(const float* __restrict__ gamma,
                                                      const float* __restrict__ beta) {
    __shared__ float Msh[KK * KK];
    int tid = threadIdx.x;
#pragma unroll
    for (int j = 0; j < KK * KK / 128; j++) Msh[tid + j * 128] = g_M[tid + j * 128];
    __syncthreads();

    int c = blockIdx.x * 128 + tid;
    float w[KK];
#pragma unroll
    for (int k = 0; k < KK; k++) w[k] = g_W2t[k * CN + c];
    float mean = 0.f;
#pragma unroll
    for (int k = 0; k < KK; k++) mean = fmaf(w[k], g_r[k], mean);
    mean /= CNT;
    float sumsq = 0.f;
#pragma unroll 2
    for (int i = 0; i < KK; i++) {
        float t = 0.f;
#pragma unroll
        for (int j = 0; j < KK; j++) t = fmaf(Msh[i * KK + j], w[j], t);
        sumsq = fmaf(w[i], t, sumsq);
    }
    float var = sumsq / CNT - mean * mean;
    float sc = gamma[c] * rsqrtf(var + BN_EPS);
    g_scale[c] = sc;
    g_shift[c] = beta[c] - mean * sc;
}

// ---------------- 5. fused: out = relu((W2 @ Atilde)*sc + sh + x) -----------
#define B_TN 128
#define B_TC 128
#define B_SMEM (KK * B_TN * 4 + 2 * KK * B_TC * 4)   // 96KB
__global__ __launch_bounds__(256) void out_fused_kernel(const float* __restrict__ x,
                                                        float* __restrict__ out) {
    extern __shared__ __align__(16) char sm_b[];
    float (*as)[B_TN]     = (float (*)[B_TN])sm_b;                          // 32KB
    float (*ws)[KK][B_TC] = (float (*)[KK][B_TC])(sm_b + KK * B_TN * 4);    // 2x32KB

    int b = blockIdx.y;
    int n0 = blockIdx.x * B_TN;
    int tid = threadIdx.x;
    int tx = tid & 15, ty = tid >> 4;
    const float* ab = g_attn + (size_t)b * KK * NPIX;

    // stage Atilde tile (2048 float4 ✓) + weight tile 0 (2048 ✓)
#pragma unroll
    for (int j = 0; j < 8; j++) {
        int i4 = tid + j * 256;
        int kk = i4 >> 5, nn4 = i4 & 31;
        cp16(&as[kk][nn4 * 4], &ab[(size_t)kk * NPIX + n0 + nn4 * 4]);
    }
#pragma unroll
    for (int j = 0; j < 8; j++) {
        int i4 = tid + j * 256;
        int kk = i4 >> 5, cc4 = i4 & 31;
        cp16(&ws[0][kk][cc4 * 4], &g_W2t[kk * CN + cc4 * 4]);
    }
    CP_COMMIT;
    CP_WAIT0;
    __syncthreads();

    for (int cb = 0; cb < CN / B_TC; cb++) {
        int cur = cb & 1;
        if (cb + 1 < CN / B_TC) {   // prefetch next weight tile
#pragma unroll
            for (int j = 0; j < 8; j++) {
                int i4 = tid + j * 256;
                int kk = i4 >> 5, cc4 = i4 & 31;
                cp16(&ws[cur ^ 1][kk][cc4 * 4],
                     &g_W2t[kk * CN + (cb + 1) * B_TC + cc4 * 4]);
            }
            CP_COMMIT;
        }
        u64 acc[8][4];
#pragma unroll
        for (int i = 0; i < 8; i++)
#pragma unroll
            for (int j = 0; j < 4; j++) acc[i][j] = 0ull;
#pragma unroll 8
        for (int kk = 0; kk < KK; kk++) {
            ulonglong2 aa = *(const ulonglong2*)&as[kk][tx * 8];
            ulonglong2 ac = *(const ulonglong2*)&as[kk][tx * 8 + 4];
            u64 av[4] = {aa.x, aa.y, ac.x, ac.y};
            float4 w0 = *(const float4*)&ws[cur][kk][ty * 8];
            float4 w1 = *(const float4*)&ws[cur][kk][ty * 8 + 4];
            u64 wv[8] = {pack2(w0.x, w0.x), pack2(w0.y, w0.y),
                         pack2(w0.z, w0.z), pack2(w0.w, w0.w),
                         pack2(w1.x, w1.x), pack2(w1.y, w1.y),
                         pack2(w1.z, w1.z), pack2(w1.w, w1.w)};
#pragma unroll
            for (int ki = 0; ki < 8; ki++)
#pragma unroll
                for (int jp = 0; jp < 4; jp++)
                    acc[ki][jp] = ffma2(wv[ki], av[jp], acc[ki][jp]);
        }
        // epilogue: BN affine, residual, relu -> out
        int c0 = cb * B_TC;
#pragma unroll
        for (int ki = 0; ki < 8; ki++) {
            int c = c0 + ty * 8 + ki;
            float sc = g_scale[c], sh = g_shift[c];
            float2 y0 = unpack2(acc[ki][0]), y1 = unpack2(acc[ki][1]);
            float2 y2 = unpack2(acc[ki][2]), y3 = unpack2(acc[ki][3]);
            size_t off = ((size_t)(b * CN + c)) * NPIX + n0 + tx * 8;
            float4 x0 = *(const float4*)&x[off];
            float4 x1 = *(const float4*)&x[off + 4];
            float4 o0, o1;
            o0.x = fmaxf(fmaf(y0.x, sc, sh) + x0.x, 0.f);
            o0.y = fmaxf(fmaf(y0.y, sc, sh) + x0.y, 0.f);
            o0.z = fmaxf(fmaf(y1.x, sc, sh) + x0.z, 0.f);
            o0.w = fmaxf(fmaf(y1.y, sc, sh) + x0.w, 0.f);
            o1.x = fmaxf(fmaf(y2.x, sc, sh) + x1.x, 0.f);
            o1.y = fmaxf(fmaf(y2.y, sc, sh) + x1.y, 0.f);
            o1.z = fmaxf(fmaf(y3.x, sc, sh) + x1.z, 0.f);
            o1.w = fmaxf(fmaf(y3.y, sc, sh) + x1.w, 0.f);
            *(float4*)&out[off] = o0;
            *(float4*)&out[off + 4] = o1;
        }
        if (cb + 1 < CN / B_TC) { CP_WAIT0; __syncthreads(); }
    }
}

// ---------------- launch -----------------------------------------------------
extern "C" void kernel_launch(void* const* d_in, const int* in_sizes, int n_in,
                              void* d_out, int out_size) {
    const float* x       = (const float*)d_in[0];
    const float* conv1_w = (const float*)d_in[1];
    const float* conv1_b = (const float*)d_in[2];
    const float* lin0_w  = (const float*)d_in[3];
    const float* lin1_w  = (const float*)d_in[4];
    const float* conv2_w = (const float*)d_in[5];
    const float* gamma   = (const float*)d_in[6];
    const float* beta    = (const float*)d_in[7];
    float* out = (float*)d_out;

    cudaFuncSetAttribute(attn_gemm_kernel,
                         cudaFuncAttributeMaxDynamicSharedMemorySize, A_SMEM);
    cudaFuncSetAttribute(stats_kernel,
                         cudaFuncAttributeMaxDynamicSharedMemorySize, S_SMEM);
    cudaFuncSetAttribute(out_fused_kernel,
                         cudaFuncAttributeMaxDynamicSharedMemorySize, B_SMEM);

    prep_kernel<<<17, 256>>>(conv1_w, conv1_b, lin0_w, lin1_w, conv2_w);
    attn_gemm_kernel<<<dim3(NPIX / A_TN, BB), 256, A_SMEM>>>(x);
    stats_kernel<<<dim3(NPIX / S_TN, BB), 256, S_SMEM>>>();
    bnscale_kernel<<<CN / 128, 128>>>(gamma, beta);
    out_fused_kernel<<<dim3(NPIX / B_TN, BB), 256, B_SMEM>>>(x, out);
}